// round 8
// baseline (speedup 1.0000x reference)
#include <cuda_runtime.h>
#include <math.h>

// ---------------------------------------------------------------------------
// VariationalDecoder: 168-step GRU decoder, B=1024, H=512, XP=256.
// Persistent batch-split kernel: 128 CTAs x 256 threads, TB=8 rows per CTA.
// Weights streamed from L2 each step (5.2MB, L2-resident). Packed f32x2 FMA.
// ---------------------------------------------------------------------------

#define L_STEPS 168
#define BATCH   1024
#define HDIM    512
#define XPDIM   256
#define XLDIM   64
#define XEDIM   16
#define FEAT    592          // HDIM + XLDIM + XEDIM
#define G3      1536         // 3 * HDIM
#define TB      8            // batch rows per CTA
#define NCTA    (BATCH / TB) // 128
#define OUTL    169          // L + 1
#define OUTC    24
#define OUT_ROW (OUTL * OUTC)          // 4056
#define NMU     ((size_t)BATCH * OUT_ROW)

// transposed-weight scratch (allowed: __device__ globals, no allocation)
__device__ float g_WihT[XPDIM * G3];   // [k=256][j=1536]
__device__ float g_WhhT[HDIM * G3];    // [k=512][j=1536]
__device__ float g_WhT [HDIM * 48];    // [k=512][o=48]  (mu cols 0..23, lv 24..47)

typedef unsigned long long u64;

__device__ __forceinline__ u64 ffma2(u64 a, u64 b, u64 c) {
    u64 d;
    asm("fma.rn.f32x2 %0, %1, %2, %3;" : "=l"(d) : "l"(a), "l"(b), "l"(c));
    return d;
}
__device__ __forceinline__ u64 splat2(float x) {
    u64 d;
    asm("mov.b64 %0, {%1, %1};" : "=l"(d) : "f"(x));
    return d;
}
__device__ __forceinline__ float2 unpack2(u64 v) {
    float2 f;
    asm("mov.b64 {%0, %1}, %2;" : "=f"(f.x), "=f"(f.y) : "l"(v));
    return f;
}
__device__ __forceinline__ float sigm(float x) { return 1.0f / (1.0f + expf(-x)); }

// ---------------------------------------------------------------------------
// Prep: transpose weights into k-major scratch (runs once per launch, ~tens us)
// ---------------------------------------------------------------------------
__global__ void prep_kernel(const float* __restrict__ Wih,
                            const float* __restrict__ Whh,
                            const float* __restrict__ Wmu,
                            const float* __restrict__ Wlv) {
    int stride = gridDim.x * blockDim.x;
    int tid = blockIdx.x * blockDim.x + threadIdx.x;
    for (int idx = tid; idx < G3 * XPDIM; idx += stride) {
        int j = idx / XPDIM, k = idx % XPDIM;
        g_WihT[k * G3 + j] = Wih[idx];
    }
    for (int idx = tid; idx < G3 * HDIM; idx += stride) {
        int j = idx / HDIM, k = idx % HDIM;
        g_WhhT[k * G3 + j] = Whh[idx];
    }
    for (int idx = tid; idx < 24 * HDIM; idx += stride) {
        int o = idx / HDIM, k = idx % HDIM;
        g_WhT[k * 48 + o]      = Wmu[idx];
        g_WhT[k * 48 + 24 + o] = Wlv[idx];
    }
}

// ---------------------------------------------------------------------------
// Heads: out[:, tstep, :] from h (stored transposed in featT[0..HDIM))
// 192 threads do split-K (4 x 128) partials, 48 threads reduce + store.
// ---------------------------------------------------------------------------
__device__ __forceinline__ void do_heads(const float* featT, float* red,
                                         float* __restrict__ out, int b0, int tstep,
                                         const float* __restrict__ bmu,
                                         const float* __restrict__ blv) {
    int t = threadIdx.x;
    __syncthreads();   // h_new visible in featT
    if (t < 192) {
        int o = t % 48;
        int p = t / 48;                    // k partition 0..3
        u64 a0 = 0, a1 = 0, a2 = 0, a3 = 0;
        const float* w = g_WhT + (p * 128) * 48 + o;
        const float* f = featT + (p * 128) * 8;
#pragma unroll 4
        for (int k = 0; k < 128; ++k) {
            ulonglong2 A = *reinterpret_cast<const ulonglong2*>(f);
            ulonglong2 B = *reinterpret_cast<const ulonglong2*>(f + 4);
            u64 ww = splat2(*w);
            a0 = ffma2(A.x, ww, a0);
            a1 = ffma2(A.y, ww, a1);
            a2 = ffma2(B.x, ww, a2);
            a3 = ffma2(B.y, ww, a3);
            f += 8; w += 48;
        }
        u64* rp = reinterpret_cast<u64*>(red + t * 8);
        rp[0] = a0; rp[1] = a1; rp[2] = a2; rp[3] = a3;
    }
    __syncthreads();
    if (t < 48) {
        float bias = (t < 24) ? bmu[t] : blv[t - 24];
        float* obase = (t < 24) ? (out + (size_t)tstep * 24 + t)
                                : (out + NMU + (size_t)tstep * 24 + (t - 24));
#pragma unroll
        for (int r = 0; r < 8; ++r) {
            float s = red[t * 8 + r] + red[(48 + t) * 8 + r] +
                      red[(96 + t) * 8 + r] + red[(144 + t) * 8 + r] + bias;
            obase[(size_t)(b0 + r) * OUT_ROW] = s;
        }
    }
}

// ---------------------------------------------------------------------------
// Main persistent kernel
// ---------------------------------------------------------------------------
__global__ void __launch_bounds__(256, 1)
decoder_kernel(const float* __restrict__ xl, const float* __restrict__ xe,
               const float* __restrict__ z,
               const float* __restrict__ bih, const float* __restrict__ bhh,
               const float* __restrict__ bmu, const float* __restrict__ blv,
               const float* __restrict__ Wtb, const float* __restrict__ btb,
               float* __restrict__ out) {
    __shared__ __align__(16) float featT[FEAT * 8];  // [k][r], k<HDIM is h
    __shared__ __align__(16) float xpT[XPDIM * 8];   // x_prime transposed
    __shared__ __align__(16) float red[192 * 8];     // heads partials

    const int t  = threadIdx.x;
    const int b0 = blockIdx.x * TB;
    const int c0 = 2 * t;                            // gate columns c0, c0+1

    // per-thread bias preload for the gate columns
    float bi[3][2], bh[3][2];
#pragma unroll
    for (int g = 0; g < 3; ++g) {
        float2 v1 = *reinterpret_cast<const float2*>(bih + 512 * g + c0);
        float2 v2 = *reinterpret_cast<const float2*>(bhh + 512 * g + c0);
        bi[g][0] = v1.x; bi[g][1] = v1.y;
        bh[g][0] = v2.x; bh[g][1] = v2.y;
    }
    const float btb_n = btb[t];

    // h <- z_latent (transposed into featT)
#pragma unroll
    for (int m = 0; m < 16; ++m) {
        int idx = t + 256 * m;          // 0..4095
        int r = idx >> 9, k = idx & 511;
        featT[k * 8 + r] = z[(size_t)(b0 + r) * HDIM + k];
    }

    do_heads(featT, red, out, b0, 0, bmu, blv);      // t = 0 heads from z

    for (int step = 0; step < L_STEPS; ++step) {
        // ---- load x_l_t, x_ext_t into featT tail -------------------------
#pragma unroll
        for (int m = 0; m < 2; ++m) {
            int idx = t + 256 * m;      // 0..511
            int r = idx >> 6, i = idx & 63;
            featT[(HDIM + i) * 8 + r] =
                xl[((size_t)(b0 + r) * L_STEPS + step) * XLDIM + i];
        }
        if (t < 128) {
            int r = t >> 4, i = t & 15;
            featT[(HDIM + XLDIM + i) * 8 + r] =
                xe[((size_t)(b0 + r) * L_STEPS + step) * XEDIM + i];
        }
        __syncthreads();

        // ---- GEMM1: x_prime[n = t] = tanh(feat @ W_tb + b) ---------------
        {
            u64 bb = splat2(btb_n);
            u64 a0 = bb, a1 = bb, a2 = bb, a3 = bb;
            const float* w = Wtb + t;
            const float* f = featT;
#pragma unroll 4
            for (int k = 0; k < FEAT; ++k) {
                ulonglong2 A = *reinterpret_cast<const ulonglong2*>(f);
                ulonglong2 B = *reinterpret_cast<const ulonglong2*>(f + 4);
                u64 ww = splat2(*w);
                a0 = ffma2(A.x, ww, a0);
                a1 = ffma2(A.y, ww, a1);
                a2 = ffma2(B.x, ww, a2);
                a3 = ffma2(B.y, ww, a3);
                f += 8; w += XPDIM;
            }
            float2 f0 = unpack2(a0), f1 = unpack2(a1);
            float2 f2 = unpack2(a2), f3 = unpack2(a3);
            *reinterpret_cast<float4*>(xpT + t * 8) =
                make_float4(tanhf(f0.x), tanhf(f0.y), tanhf(f1.x), tanhf(f1.y));
            *reinterpret_cast<float4*>(xpT + t * 8 + 4) =
                make_float4(tanhf(f2.x), tanhf(f2.y), tanhf(f3.x), tanhf(f3.y));
        }
        __syncthreads();

        // ---- Phase C: GRU gate GEMMs, cols c0 and c0+1 -------------------
        u64 gi[3][2][4], gh[3][2][4];   // [gate][col][rowpair]
#pragma unroll
        for (int g = 0; g < 3; ++g)
#pragma unroll
            for (int cc = 0; cc < 2; ++cc)
#pragma unroll
                for (int p = 0; p < 4; ++p) { gi[g][cc][p] = 0ull; gh[g][cc][p] = 0ull; }

        {   // gi = x_prime @ W_ih^T  (K = 256)
            const float* f = xpT;
            const float* w = g_WihT + c0;
#pragma unroll 2
            for (int k = 0; k < XPDIM; ++k) {
                ulonglong2 A = *reinterpret_cast<const ulonglong2*>(f);
                ulonglong2 B = *reinterpret_cast<const ulonglong2*>(f + 4);
                u64 a0 = A.x, a1 = A.y, a2 = B.x, a3 = B.y;
#pragma unroll
                for (int g = 0; g < 3; ++g) {
                    float2 wv = *reinterpret_cast<const float2*>(w + 512 * g);
                    u64 w0 = splat2(wv.x), w1 = splat2(wv.y);
                    gi[g][0][0] = ffma2(a0, w0, gi[g][0][0]);
                    gi[g][0][1] = ffma2(a1, w0, gi[g][0][1]);
                    gi[g][0][2] = ffma2(a2, w0, gi[g][0][2]);
                    gi[g][0][3] = ffma2(a3, w0, gi[g][0][3]);
                    gi[g][1][0] = ffma2(a0, w1, gi[g][1][0]);
                    gi[g][1][1] = ffma2(a1, w1, gi[g][1][1]);
                    gi[g][1][2] = ffma2(a2, w1, gi[g][1][2]);
                    gi[g][1][3] = ffma2(a3, w1, gi[g][1][3]);
                }
                f += 8; w += G3;
            }
        }
        {   // gh = h @ W_hh^T  (K = 512)
            const float* f = featT;
            const float* w = g_WhhT + c0;
#pragma unroll 2
            for (int k = 0; k < HDIM; ++k) {
                ulonglong2 A = *reinterpret_cast<const ulonglong2*>(f);
                ulonglong2 B = *reinterpret_cast<const ulonglong2*>(f + 4);
                u64 a0 = A.x, a1 = A.y, a2 = B.x, a3 = B.y;
#pragma unroll
                for (int g = 0; g < 3; ++g) {
                    float2 wv = *reinterpret_cast<const float2*>(w + 512 * g);
                    u64 w0 = splat2(wv.x), w1 = splat2(wv.y);
                    gh[g][0][0] = ffma2(a0, w0, gh[g][0][0]);
                    gh[g][0][1] = ffma2(a1, w0, gh[g][0][1]);
                    gh[g][0][2] = ffma2(a2, w0, gh[g][0][2]);
                    gh[g][0][3] = ffma2(a3, w0, gh[g][0][3]);
                    gh[g][1][0] = ffma2(a0, w1, gh[g][1][0]);
                    gh[g][1][1] = ffma2(a1, w1, gh[g][1][1]);
                    gh[g][1][2] = ffma2(a2, w1, gh[g][1][2]);
                    gh[g][1][3] = ffma2(a3, w1, gh[g][1][3]);
                }
                f += 8; w += G3;
            }
        }

        // ---- gates + h_new (registers) ------------------------------------
        float hn[2][8];
#pragma unroll
        for (int cc = 0; cc < 2; ++cc) {
#pragma unroll
            for (int p = 0; p < 4; ++p) {
                float2 ir = unpack2(gi[0][cc][p]), hr = unpack2(gh[0][cc][p]);
                float2 iz = unpack2(gi[1][cc][p]), hz = unpack2(gh[1][cc][p]);
                float2 in = unpack2(gi[2][cc][p]), hnv = unpack2(gh[2][cc][p]);
                float rx = sigm(ir.x + bi[0][cc] + hr.x + bh[0][cc]);
                float ry = sigm(ir.y + bi[0][cc] + hr.y + bh[0][cc]);
                float zx = sigm(iz.x + bi[1][cc] + hz.x + bh[1][cc]);
                float zy = sigm(iz.y + bi[1][cc] + hz.y + bh[1][cc]);
                float nx = tanhf(in.x + bi[2][cc] + rx * (hnv.x + bh[2][cc]));
                float ny = tanhf(in.y + bi[2][cc] + ry * (hnv.y + bh[2][cc]));
                float hx = featT[(c0 + cc) * 8 + 2 * p];
                float hy = featT[(c0 + cc) * 8 + 2 * p + 1];
                hn[cc][2 * p]     = nx + zx * (hx - nx);   // (1-z)*n + z*h
                hn[cc][2 * p + 1] = ny + zy * (hy - ny);
            }
        }
        __syncthreads();   // everyone done reading old h
        *reinterpret_cast<float4*>(featT + c0 * 8) =
            make_float4(hn[0][0], hn[0][1], hn[0][2], hn[0][3]);
        *reinterpret_cast<float4*>(featT + c0 * 8 + 4) =
            make_float4(hn[0][4], hn[0][5], hn[0][6], hn[0][7]);
        *reinterpret_cast<float4*>(featT + c0 * 8 + 8) =
            make_float4(hn[1][0], hn[1][1], hn[1][2], hn[1][3]);
        *reinterpret_cast<float4*>(featT + c0 * 8 + 12) =
            make_float4(hn[1][4], hn[1][5], hn[1][6], hn[1][7]);

        do_heads(featT, red, out, b0, step + 1, bmu, blv);  // starts with sync
    }
}

// ---------------------------------------------------------------------------
extern "C" void kernel_launch(void* const* d_in, const int* in_sizes, int n_in,
                              void* d_out, int out_size) {
    const float* xl  = (const float*)d_in[0];   // x_l_seq   [1024,168,64]
    const float* xe  = (const float*)d_in[1];   // x_ext_seq [1024,168,16]
    const float* z   = (const float*)d_in[2];   // z_latent  [1024,512]
    const float* Wih = (const float*)d_in[3];   // [1536,256]
    const float* Whh = (const float*)d_in[4];   // [1536,512]
    const float* bih = (const float*)d_in[5];   // [1536]
    const float* bhh = (const float*)d_in[6];   // [1536]
    const float* Wmu = (const float*)d_in[7];   // [24,512]
    const float* bmu = (const float*)d_in[8];   // [24]
    const float* Wlv = (const float*)d_in[9];   // [24,512]
    const float* blv = (const float*)d_in[10];  // [24]
    const float* Wtb = (const float*)d_in[11];  // [592,256]
    const float* btb = (const float*)d_in[12];  // [256]
    float* out = (float*)d_out;                 // mu [1024,169,24] then lv

    prep_kernel<<<256, 256>>>(Wih, Whh, Wmu, Wlv);
    decoder_kernel<<<NCTA, 256>>>(xl, xe, z, bih, bhh, bmu, blv, Wtb, btb, out);
}

// round 9
// speedup vs baseline: 1.5468x; 1.5468x over previous
#include <cuda_runtime.h>
#include <math.h>

// ---------------------------------------------------------------------------
// VariationalDecoder: 168-step GRU decoder, B=1024, H=512, XP=256.
// Persistent batch-split kernel: 128 CTAs x 512 threads, TB=8 rows per CTA.
// Each thread owns ONE gate column across all 3 gates (4 warps/SMSP for
// latency hiding). Weights streamed from L2 each step. Packed f32x2 FMA.
// ---------------------------------------------------------------------------

#define L_STEPS 168
#define BATCH   1024
#define HDIM    512
#define XPDIM   256
#define XLDIM   64
#define XEDIM   16
#define FEAT    592          // HDIM + XLDIM + XEDIM
#define G3      1536         // 3 * HDIM
#define TB      8            // batch rows per CTA
#define NCTA    (BATCH / TB) // 128
#define NT      512          // threads per CTA
#define OUTL    169          // L + 1
#define OUTC    24
#define OUT_ROW (OUTL * OUTC)          // 4056
#define NMU     ((size_t)BATCH * OUT_ROW)
#define KH1     296          // 592 / 2 for GEMM1 split-K

// transposed-weight scratch (allowed: __device__ globals, no allocation)
__device__ float g_WihT[XPDIM * G3];   // [k=256][j=1536]  (j = gate*512 + col)
__device__ float g_WhhT[HDIM * G3];    // [k=512][j=1536]
__device__ float g_WhT [HDIM * 48];    // [k=512][o=48]  (mu 0..23, lv 24..47)

typedef unsigned long long u64;

__device__ __forceinline__ u64 ffma2(u64 a, u64 b, u64 c) {
    u64 d;
    asm("fma.rn.f32x2 %0, %1, %2, %3;" : "=l"(d) : "l"(a), "l"(b), "l"(c));
    return d;
}
__device__ __forceinline__ u64 splat2(float x) {
    u64 d;
    asm("mov.b64 %0, {%1, %1};" : "=l"(d) : "f"(x));
    return d;
}
__device__ __forceinline__ float2 unpack2(u64 v) {
    float2 f;
    asm("mov.b64 {%0, %1}, %2;" : "=f"(f.x), "=f"(f.y) : "l"(v));
    return f;
}
__device__ __forceinline__ float sigm(float x) { return 1.0f / (1.0f + expf(-x)); }

// ---------------------------------------------------------------------------
// Prep: transpose weights into k-major scratch (once per launch)
// ---------------------------------------------------------------------------
__global__ void prep_kernel(const float* __restrict__ Wih,
                            const float* __restrict__ Whh,
                            const float* __restrict__ Wmu,
                            const float* __restrict__ Wlv) {
    int stride = gridDim.x * blockDim.x;
    int tid = blockIdx.x * blockDim.x + threadIdx.x;
    for (int idx = tid; idx < G3 * XPDIM; idx += stride) {
        int j = idx / XPDIM, k = idx % XPDIM;
        g_WihT[k * G3 + j] = Wih[idx];
    }
    for (int idx = tid; idx < G3 * HDIM; idx += stride) {
        int j = idx / HDIM, k = idx % HDIM;
        g_WhhT[k * G3 + j] = Whh[idx];
    }
    for (int idx = tid; idx < 24 * HDIM; idx += stride) {
        int o = idx / HDIM, k = idx % HDIM;
        g_WhT[k * 48 + o]      = Wmu[idx];
        g_WhT[k * 48 + 24 + o] = Wlv[idx];
    }
}

// ---------------------------------------------------------------------------
// Heads: out[:, tstep, :] from h (stored transposed in featT[0..HDIM))
// 384 threads do split-K (8 x 64) partials, 48 threads reduce + store.
// ---------------------------------------------------------------------------
__device__ __forceinline__ void do_heads(const float* featT, float* red,
                                         float* __restrict__ out, int b0, int tstep,
                                         const float* __restrict__ bmu,
                                         const float* __restrict__ blv) {
    int t = threadIdx.x;
    __syncthreads();   // h_new visible in featT
    if (t < 384) {
        int o = t % 48;
        int p = t / 48;                    // k partition 0..7
        u64 a0 = 0, a1 = 0, a2 = 0, a3 = 0;
        const float* w = g_WhT + (p * 64) * 48 + o;
        const float* f = featT + (p * 64) * 8;
#pragma unroll 4
        for (int k = 0; k < 64; ++k) {
            ulonglong2 A = *reinterpret_cast<const ulonglong2*>(f);
            ulonglong2 B = *reinterpret_cast<const ulonglong2*>(f + 4);
            u64 ww = splat2(*w);
            a0 = ffma2(A.x, ww, a0);
            a1 = ffma2(A.y, ww, a1);
            a2 = ffma2(B.x, ww, a2);
            a3 = ffma2(B.y, ww, a3);
            f += 8; w += 48;
        }
        u64* rp = reinterpret_cast<u64*>(red + t * 8);
        rp[0] = a0; rp[1] = a1; rp[2] = a2; rp[3] = a3;
    }
    __syncthreads();
    if (t < 48) {
        float bias = (t < 24) ? bmu[t] : blv[t - 24];
        float* obase = (t < 24) ? (out + (size_t)tstep * 24 + t)
                                : (out + NMU + (size_t)tstep * 24 + (t - 24));
#pragma unroll
        for (int r = 0; r < 8; ++r) {
            float s = bias;
#pragma unroll
            for (int p = 0; p < 8; ++p)
                s += red[(p * 48 + t) * 8 + r];
            obase[(size_t)(b0 + r) * OUT_ROW] = s;
        }
    }
}

// ---------------------------------------------------------------------------
// Main persistent kernel
// ---------------------------------------------------------------------------
__global__ void __launch_bounds__(NT, 1)
decoder_kernel(const float* __restrict__ xl, const float* __restrict__ xe,
               const float* __restrict__ z,
               const float* __restrict__ bih, const float* __restrict__ bhh,
               const float* __restrict__ bmu, const float* __restrict__ blv,
               const float* __restrict__ Wtb, const float* __restrict__ btb,
               float* __restrict__ out) {
    __shared__ __align__(16) float featT[FEAT * 8];  // [k][r], k<HDIM is h
    __shared__ __align__(16) float xpT[XPDIM * 8];   // x_prime transposed
    __shared__ __align__(16) float red[NT * 8];      // split-K partials

    const int t  = threadIdx.x;
    const int b0 = blockIdx.x * TB;
    const int c  = t;                  // this thread's gate column (0..511)

    // per-thread bias preload for the gate column
    float bi[3], bh[3];
#pragma unroll
    for (int g = 0; g < 3; ++g) {
        bi[g] = bih[512 * g + c];
        bh[g] = bhh[512 * g + c];
    }
    // GEMM1 split-K mapping
    const int n1 = t & 255;            // x_prime column
    const int h1 = t >> 8;             // K half (0/1)
    const float btb_n = btb[n1];

    // h <- z_latent (transposed into featT)
#pragma unroll
    for (int m = 0; m < 8; ++m) {
        int idx = t + NT * m;           // 0..4095
        int r = idx >> 9, k = idx & 511;
        featT[k * 8 + r] = z[(size_t)(b0 + r) * HDIM + k];
    }

    do_heads(featT, red, out, b0, 0, bmu, blv);      // t = 0 heads from z

    for (int step = 0; step < L_STEPS; ++step) {
        // ---- load x_l_t, x_ext_t into featT tail -------------------------
        {
            int r = t >> 6, i = t & 63; // 512 values, one per thread
            featT[(HDIM + i) * 8 + r] =
                xl[((size_t)(b0 + r) * L_STEPS + step) * XLDIM + i];
        }
        if (t < 128) {
            int r = t >> 4, i = t & 15;
            featT[(HDIM + XLDIM + i) * 8 + r] =
                xe[((size_t)(b0 + r) * L_STEPS + step) * XEDIM + i];
        }
        __syncthreads();

        // ---- GEMM1 (split-K x2): x_prime[n] = tanh(feat @ W_tb + b) ------
        {
            u64 a0 = 0, a1 = 0, a2 = 0, a3 = 0;
            const float* w = Wtb + (size_t)h1 * KH1 * XPDIM + n1;
            const float* f = featT + h1 * KH1 * 8;
#pragma unroll 4
            for (int k = 0; k < KH1; ++k) {
                ulonglong2 A = *reinterpret_cast<const ulonglong2*>(f);
                ulonglong2 B = *reinterpret_cast<const ulonglong2*>(f + 4);
                u64 ww = splat2(*w);
                a0 = ffma2(A.x, ww, a0);
                a1 = ffma2(A.y, ww, a1);
                a2 = ffma2(B.x, ww, a2);
                a3 = ffma2(B.y, ww, a3);
                f += 8; w += XPDIM;
            }
            u64* rp = reinterpret_cast<u64*>(red + t * 8);
            rp[0] = a0; rp[1] = a1; rp[2] = a2; rp[3] = a3;
        }
        __syncthreads();
        if (t < 256) {
#pragma unroll
            for (int j = 0; j < 8; ++j) {
                float s = red[t * 8 + j] + red[(256 + t) * 8 + j] + btb_n;
                xpT[t * 8 + j] = tanhf(s);
            }
        }
        __syncthreads();

        // ---- GRU gate GEMMs: column c, gates r/z/n ------------------------
        u64 gi[3][4], gh[3][4];         // [gate][rowpair]
#pragma unroll
        for (int g = 0; g < 3; ++g)
#pragma unroll
            for (int p = 0; p < 4; ++p) { gi[g][p] = 0ull; gh[g][p] = 0ull; }

        {   // gi = x_prime @ W_ih^T  (K = 256)
            const float* f = xpT;
            const float* w = g_WihT + c;
#pragma unroll 4
            for (int k = 0; k < XPDIM; ++k) {
                ulonglong2 A = *reinterpret_cast<const ulonglong2*>(f);
                ulonglong2 B = *reinterpret_cast<const ulonglong2*>(f + 4);
#pragma unroll
                for (int g = 0; g < 3; ++g) {
                    u64 ww = splat2(w[512 * g]);
                    gi[g][0] = ffma2(A.x, ww, gi[g][0]);
                    gi[g][1] = ffma2(A.y, ww, gi[g][1]);
                    gi[g][2] = ffma2(B.x, ww, gi[g][2]);
                    gi[g][3] = ffma2(B.y, ww, gi[g][3]);
                }
                f += 8; w += G3;
            }
        }
        {   // gh = h @ W_hh^T  (K = 512)
            const float* f = featT;
            const float* w = g_WhhT + c;
#pragma unroll 4
            for (int k = 0; k < HDIM; ++k) {
                ulonglong2 A = *reinterpret_cast<const ulonglong2*>(f);
                ulonglong2 B = *reinterpret_cast<const ulonglong2*>(f + 4);
#pragma unroll
                for (int g = 0; g < 3; ++g) {
                    u64 ww = splat2(w[512 * g]);
                    gh[g][0] = ffma2(A.x, ww, gh[g][0]);
                    gh[g][1] = ffma2(A.y, ww, gh[g][1]);
                    gh[g][2] = ffma2(B.x, ww, gh[g][2]);
                    gh[g][3] = ffma2(B.y, ww, gh[g][3]);
                }
                f += 8; w += G3;
            }
        }

        // ---- gates + h_new (registers) ------------------------------------
        float hn[8];
#pragma unroll
        for (int p = 0; p < 4; ++p) {
            float2 ir = unpack2(gi[0][p]), hr = unpack2(gh[0][p]);
            float2 iz = unpack2(gi[1][p]), hz = unpack2(gh[1][p]);
            float2 in = unpack2(gi[2][p]), hv = unpack2(gh[2][p]);
            float rx = sigm(ir.x + bi[0] + hr.x + bh[0]);
            float ry = sigm(ir.y + bi[0] + hr.y + bh[0]);
            float zx = sigm(iz.x + bi[1] + hz.x + bh[1]);
            float zy = sigm(iz.y + bi[1] + hz.y + bh[1]);
            float nx = tanhf(in.x + bi[2] + rx * (hv.x + bh[2]));
            float ny = tanhf(in.y + bi[2] + ry * (hv.y + bh[2]));
            float hx = featT[c * 8 + 2 * p];
            float hy = featT[c * 8 + 2 * p + 1];
            hn[2 * p]     = nx + zx * (hx - nx);   // (1-z)*n + z*h
            hn[2 * p + 1] = ny + zy * (hy - ny);
        }
        __syncthreads();   // everyone done reading old h
        *reinterpret_cast<float4*>(featT + c * 8) =
            make_float4(hn[0], hn[1], hn[2], hn[3]);
        *reinterpret_cast<float4*>(featT + c * 8 + 4) =
            make_float4(hn[4], hn[5], hn[6], hn[7]);

        do_heads(featT, red, out, b0, step + 1, bmu, blv);  // starts with sync
    }
}

// ---------------------------------------------------------------------------
extern "C" void kernel_launch(void* const* d_in, const int* in_sizes, int n_in,
                              void* d_out, int out_size) {
    const float* xl  = (const float*)d_in[0];   // x_l_seq   [1024,168,64]
    const float* xe  = (const float*)d_in[1];   // x_ext_seq [1024,168,16]
    const float* z   = (const float*)d_in[2];   // z_latent  [1024,512]
    const float* Wih = (const float*)d_in[3];   // [1536,256]
    const float* Whh = (const float*)d_in[4];   // [1536,512]
    const float* bih = (const float*)d_in[5];   // [1536]
    const float* bhh = (const float*)d_in[6];   // [1536]
    const float* Wmu = (const float*)d_in[7];   // [24,512]
    const float* bmu = (const float*)d_in[8];   // [24]
    const float* Wlv = (const float*)d_in[9];   // [24,512]
    const float* blv = (const float*)d_in[10];  // [24]
    const float* Wtb = (const float*)d_in[11];  // [592,256]
    const float* btb = (const float*)d_in[12];  // [256]
    float* out = (float*)d_out;                 // mu [1024,169,24] then lv

    prep_kernel<<<256, 256>>>(Wih, Whh, Wmu, Wlv);
    decoder_kernel<<<NCTA, NT>>>(xl, xe, z, bih, bhh, bmu, blv, Wtb, btb, out);
}

// round 10
// speedup vs baseline: 2.0532x; 1.3274x over previous
#include <cuda_runtime.h>
#include <math.h>

// ---------------------------------------------------------------------------
// VariationalDecoder: 168-step GRU decoder, B=1024, H=512, XP=256.
// 128 CTAs x 512 threads, TB=8 batch rows per CTA, one gate-column per thread.
// Weights k2-packed (float2 over adjacent k) + register double-buffer prefetch
// to hide L2 latency. Fused r/z accumulators keep regs under the 128 cap.
// ---------------------------------------------------------------------------

#define L_STEPS 168
#define BATCH   1024
#define HDIM    512
#define XPDIM   256
#define XLDIM   64
#define XEDIM   16
#define FEAT    592          // HDIM + XLDIM + XEDIM
#define G3      1536         // 3 * HDIM
#define TB      8
#define NCTA    (BATCH / TB) // 128
#define NT      512
#define OUTL    169
#define OUTC    24
#define OUT_ROW (OUTL * OUTC)          // 4056
#define NMU     ((size_t)BATCH * OUT_ROW)

// k2-packed weights: element [k2][j] = {W[2k2][j-ish], W[2k2+1][...]} (float2)
__device__ float2 g_WihP[128 * G3];     // K=256 -> 128 k2
__device__ float2 g_WhhP[256 * G3];     // K=512 -> 256 k2
__device__ float2 g_WtbP[296 * XPDIM];  // K=592 -> 296 k2
__device__ float2 g_WhP [256 * 48];     // heads K=512 -> 256 k2

typedef unsigned long long u64;

__device__ __forceinline__ u64 ffma2(u64 a, u64 b, u64 c) {
    u64 d;
    asm("fma.rn.f32x2 %0, %1, %2, %3;" : "=l"(d) : "l"(a), "l"(b), "l"(c));
    return d;
}
__device__ __forceinline__ u64 splat2(float x) {
    u64 d;
    asm("mov.b64 %0, {%1, %1};" : "=l"(d) : "f"(x));
    return d;
}
__device__ __forceinline__ float2 unpack2(u64 v) {
    float2 f;
    asm("mov.b64 {%0, %1}, %2;" : "=f"(f.x), "=f"(f.y) : "l"(v));
    return f;
}
__device__ __forceinline__ float sigm(float x) { return 1.0f / (1.0f + expf(-x)); }

// ---------------------------------------------------------------------------
// Prep: k2-pack all weights (once per launch)
// ---------------------------------------------------------------------------
__global__ void prep_kernel(const float* __restrict__ Wih,
                            const float* __restrict__ Whh,
                            const float* __restrict__ Wmu,
                            const float* __restrict__ Wlv,
                            const float* __restrict__ Wtb) {
    int stride = gridDim.x * blockDim.x;
    int tid = blockIdx.x * blockDim.x + threadIdx.x;
    for (int idx = tid; idx < 128 * G3; idx += stride) {
        int k2 = idx / G3, j = idx % G3;
        g_WihP[idx] = make_float2(Wih[j * XPDIM + 2 * k2], Wih[j * XPDIM + 2 * k2 + 1]);
    }
    for (int idx = tid; idx < 256 * G3; idx += stride) {
        int k2 = idx / G3, j = idx % G3;
        g_WhhP[idx] = make_float2(Whh[j * HDIM + 2 * k2], Whh[j * HDIM + 2 * k2 + 1]);
    }
    for (int idx = tid; idx < 296 * XPDIM; idx += stride) {
        int k2 = idx / XPDIM, n = idx % XPDIM;
        g_WtbP[idx] = make_float2(Wtb[(2 * k2) * XPDIM + n], Wtb[(2 * k2 + 1) * XPDIM + n]);
    }
    for (int idx = tid; idx < 256 * 48; idx += stride) {
        int k2 = idx / 48, o = idx % 48;
        const float* Wh = (o < 24) ? (Wmu + o * HDIM) : (Wlv + (o - 24) * HDIM);
        g_WhP[idx] = make_float2(Wh[2 * k2], Wh[2 * k2 + 1]);
    }
}

// ---------------------------------------------------------------------------
// Gate-loop building blocks: register double-buffer prefetch
// ---------------------------------------------------------------------------
__device__ __forceinline__ void loadw(float2 (&wb)[3][2], const float2* w) {
#pragma unroll
    for (int q = 0; q < 2; ++q)
#pragma unroll
        for (int g = 0; g < 3; ++g)
            wb[g][q] = w[q * G3 + g * 512];
}

// process 2 k2 (= 4 k rows) for 3 gates: R, Z accumulate; N into aN
__device__ __forceinline__ void proc_k2(const float*& f, const float2 (&wb)[3][2],
                                        u64 (&aR)[4], u64 (&aZ)[4], u64 (&aN)[4]) {
#pragma unroll
    for (int q = 0; q < 2; ++q) {
        ulonglong2 A0 = *reinterpret_cast<const ulonglong2*>(f);
        ulonglong2 B0 = *reinterpret_cast<const ulonglong2*>(f + 4);
        ulonglong2 A1 = *reinterpret_cast<const ulonglong2*>(f + 8);
        ulonglong2 B1 = *reinterpret_cast<const ulonglong2*>(f + 12);
        f += 16;
        u64 w;
        w = splat2(wb[0][q].x);
        aR[0] = ffma2(A0.x, w, aR[0]); aR[1] = ffma2(A0.y, w, aR[1]);
        aR[2] = ffma2(B0.x, w, aR[2]); aR[3] = ffma2(B0.y, w, aR[3]);
        w = splat2(wb[0][q].y);
        aR[0] = ffma2(A1.x, w, aR[0]); aR[1] = ffma2(A1.y, w, aR[1]);
        aR[2] = ffma2(B1.x, w, aR[2]); aR[3] = ffma2(B1.y, w, aR[3]);
        w = splat2(wb[1][q].x);
        aZ[0] = ffma2(A0.x, w, aZ[0]); aZ[1] = ffma2(A0.y, w, aZ[1]);
        aZ[2] = ffma2(B0.x, w, aZ[2]); aZ[3] = ffma2(B0.y, w, aZ[3]);
        w = splat2(wb[1][q].y);
        aZ[0] = ffma2(A1.x, w, aZ[0]); aZ[1] = ffma2(A1.y, w, aZ[1]);
        aZ[2] = ffma2(B1.x, w, aZ[2]); aZ[3] = ffma2(B1.y, w, aZ[3]);
        w = splat2(wb[2][q].x);
        aN[0] = ffma2(A0.x, w, aN[0]); aN[1] = ffma2(A0.y, w, aN[1]);
        aN[2] = ffma2(B0.x, w, aN[2]); aN[3] = ffma2(B0.y, w, aN[3]);
        w = splat2(wb[2][q].y);
        aN[0] = ffma2(A1.x, w, aN[0]); aN[1] = ffma2(A1.y, w, aN[1]);
        aN[2] = ffma2(B1.x, w, aN[2]); aN[3] = ffma2(B1.y, w, aN[3]);
    }
}

// single-output version for GEMM1 (2 k2 per call)
__device__ __forceinline__ void proc1_k2(const float*& f, const float2 (&wb)[2],
                                         u64 (&a)[4]) {
#pragma unroll
    for (int q = 0; q < 2; ++q) {
        ulonglong2 A0 = *reinterpret_cast<const ulonglong2*>(f);
        ulonglong2 B0 = *reinterpret_cast<const ulonglong2*>(f + 4);
        ulonglong2 A1 = *reinterpret_cast<const ulonglong2*>(f + 8);
        ulonglong2 B1 = *reinterpret_cast<const ulonglong2*>(f + 12);
        f += 16;
        u64 w0 = splat2(wb[q].x), w1 = splat2(wb[q].y);
        a[0] = ffma2(A0.x, w0, a[0]); a[1] = ffma2(A0.y, w0, a[1]);
        a[2] = ffma2(B0.x, w0, a[2]); a[3] = ffma2(B0.y, w0, a[3]);
        a[0] = ffma2(A1.x, w1, a[0]); a[1] = ffma2(A1.y, w1, a[1]);
        a[2] = ffma2(B1.x, w1, a[2]); a[3] = ffma2(B1.y, w1, a[3]);
    }
}

// ---------------------------------------------------------------------------
// Heads: 384 threads split-K (8 x 64), 48 threads reduce + store
// ---------------------------------------------------------------------------
__device__ __forceinline__ void do_heads(const float* featT, float* red,
                                         float* __restrict__ out, int b0, int tstep,
                                         const float* __restrict__ bmu,
                                         const float* __restrict__ blv) {
    int t = threadIdx.x;
    __syncthreads();   // h_new visible in featT
    if (t < 384) {
        int o = t % 48;
        int p = t / 48;                    // k partition 0..7
        u64 a0 = 0, a1 = 0, a2 = 0, a3 = 0;
        const float2* w = g_WhP + (p * 32) * 48 + o;
        const float* f = featT + (p * 64) * 8;
#pragma unroll 4
        for (int k2 = 0; k2 < 32; ++k2) {
            ulonglong2 A0 = *reinterpret_cast<const ulonglong2*>(f);
            ulonglong2 B0 = *reinterpret_cast<const ulonglong2*>(f + 4);
            ulonglong2 A1 = *reinterpret_cast<const ulonglong2*>(f + 8);
            ulonglong2 B1 = *reinterpret_cast<const ulonglong2*>(f + 12);
            float2 wv = *w;
            u64 w0 = splat2(wv.x), w1 = splat2(wv.y);
            a0 = ffma2(A0.x, w0, a0); a1 = ffma2(A0.y, w0, a1);
            a2 = ffma2(B0.x, w0, a2); a3 = ffma2(B0.y, w0, a3);
            a0 = ffma2(A1.x, w1, a0); a1 = ffma2(A1.y, w1, a1);
            a2 = ffma2(B1.x, w1, a2); a3 = ffma2(B1.y, w1, a3);
            f += 16; w += 48;
        }
        u64* rp = reinterpret_cast<u64*>(red + t * 8);
        rp[0] = a0; rp[1] = a1; rp[2] = a2; rp[3] = a3;
    }
    __syncthreads();
    if (t < 48) {
        float bias = (t < 24) ? bmu[t] : blv[t - 24];
        float* obase = (t < 24) ? (out + (size_t)tstep * 24 + t)
                                : (out + NMU + (size_t)tstep * 24 + (t - 24));
#pragma unroll
        for (int r = 0; r < 8; ++r) {
            float s = bias;
#pragma unroll
            for (int p = 0; p < 8; ++p)
                s += red[(p * 48 + t) * 8 + r];
            obase[(size_t)(b0 + r) * OUT_ROW] = s;
        }
    }
}

// ---------------------------------------------------------------------------
// Main persistent kernel
// ---------------------------------------------------------------------------
__global__ void __launch_bounds__(NT, 1)
decoder_kernel(const float* __restrict__ xl, const float* __restrict__ xe,
               const float* __restrict__ z,
               const float* __restrict__ bih, const float* __restrict__ bhh,
               const float* __restrict__ bmu, const float* __restrict__ blv,
               const float* __restrict__ btb,
               float* __restrict__ out) {
    __shared__ __align__(16) float featT[FEAT * 8];  // [k][r], k<HDIM is h
    __shared__ __align__(16) float xpT[XPDIM * 8];   // x_prime transposed
    __shared__ __align__(16) float red[NT * 8];      // split-K partials

    const int t  = threadIdx.x;
    const int b0 = blockIdx.x * TB;
    const int c  = t;                  // this thread's gate column (0..511)

    // fused biases: r,z use (b_ih + b_hh); n keeps them separate
    const float brz_r = bih[c]        + bhh[c];
    const float brz_z = bih[512 + c]  + bhh[512 + c];
    const float bn_i  = bih[1024 + c];
    const float bn_h  = bhh[1024 + c];

    // GEMM1 split-K mapping
    const int n1 = t & 255;            // x_prime column
    const int h1 = t >> 8;             // K half (0/1)
    const float btb_n = btb[n1];

    // h <- z_latent (transposed into featT)
#pragma unroll
    for (int m = 0; m < 8; ++m) {
        int idx = t + NT * m;           // 0..4095
        int r = idx >> 9, k = idx & 511;
        featT[k * 8 + r] = z[(size_t)(b0 + r) * HDIM + k];
    }

    do_heads(featT, red, out, b0, 0, bmu, blv);      // t = 0 heads from z

    for (int step = 0; step < L_STEPS; ++step) {
        // ---- load x_l_t, x_ext_t into featT tail -------------------------
        {
            int r = t >> 6, i = t & 63;
            featT[(HDIM + i) * 8 + r] =
                xl[((size_t)(b0 + r) * L_STEPS + step) * XLDIM + i];
        }
        if (t < 128) {
            int r = t >> 4, i = t & 15;
            featT[(HDIM + XLDIM + i) * 8 + r] =
                xe[((size_t)(b0 + r) * L_STEPS + step) * XEDIM + i];
        }
        __syncthreads();

        // ---- GEMM1 (split-K x2, prefetched): x_prime = tanh(feat@Wtb+b) --
        {
            u64 a[4] = {0ull, 0ull, 0ull, 0ull};
            const float2* w = g_WtbP + (size_t)h1 * 148 * XPDIM + n1;
            const float* f = featT + h1 * 296 * 8;
            float2 wA[2], wB[2];
            wA[0] = w[0]; wA[1] = w[XPDIM]; w += 2 * XPDIM;
#pragma unroll 1
            for (int blk = 0; blk < 74; blk += 2) {
                wB[0] = w[0]; wB[1] = w[XPDIM]; w += 2 * XPDIM;
                proc1_k2(f, wA, a);
                if (blk + 2 < 74) { wA[0] = w[0]; wA[1] = w[XPDIM]; w += 2 * XPDIM; }
                proc1_k2(f, wB, a);
            }
            u64* rp = reinterpret_cast<u64*>(red + t * 8);
            rp[0] = a[0]; rp[1] = a[1]; rp[2] = a[2]; rp[3] = a[3];
        }
        __syncthreads();
        if (t < 256) {
#pragma unroll
            for (int j = 0; j < 8; ++j) {
                float s = red[t * 8 + j] + red[(256 + t) * 8 + j] + btb_n;
                xpT[t * 8 + j] = tanhf(s);
            }
        }
        __syncthreads();

        // ---- GRU gate GEMMs (fused r/z accumulators, prefetched) ----------
        u64 aR[4], aZ[4], aNi[4], aNh[4];
        {
            u64 br = splat2(brz_r), bz = splat2(brz_z), bn = splat2(bn_i);
#pragma unroll
            for (int p = 0; p < 4; ++p) { aR[p] = br; aZ[p] = bz; aNi[p] = bn; }
        }
        {   // x_prime @ W_ih^T  (128 k2)
            const float2* w = g_WihP + c;
            const float* f = xpT;
            float2 wbA[3][2], wbB[3][2];
            loadw(wbA, w); w += 2 * G3;
#pragma unroll 1
            for (int blk = 0; blk < 64; blk += 2) {
                loadw(wbB, w); w += 2 * G3;
                proc_k2(f, wbA, aR, aZ, aNi);
                if (blk + 2 < 64) { loadw(wbA, w); w += 2 * G3; }
                proc_k2(f, wbB, aR, aZ, aNi);
            }
        }
        {
            u64 bn = splat2(bn_h);
#pragma unroll
            for (int p = 0; p < 4; ++p) aNh[p] = bn;
        }
        {   // h @ W_hh^T  (256 k2)
            const float2* w = g_WhhP + c;
            const float* f = featT;
            float2 wbA[3][2], wbB[3][2];
            loadw(wbA, w); w += 2 * G3;
#pragma unroll 1
            for (int blk = 0; blk < 128; blk += 2) {
                loadw(wbB, w); w += 2 * G3;
                proc_k2(f, wbA, aR, aZ, aNh);
                if (blk + 2 < 128) { loadw(wbA, w); w += 2 * G3; }
                proc_k2(f, wbB, aR, aZ, aNh);
            }
        }

        // ---- gates + h_new (registers) ------------------------------------
        float hn[8];
#pragma unroll
        for (int p = 0; p < 4; ++p) {
            float2 rr = unpack2(aR[p]);
            float2 zz = unpack2(aZ[p]);
            float2 ni = unpack2(aNi[p]);
            float2 nh = unpack2(aNh[p]);
            float rx = sigm(rr.x), ry = sigm(rr.y);
            float zx = sigm(zz.x), zy = sigm(zz.y);
            float nx = tanhf(ni.x + rx * nh.x);
            float ny = tanhf(ni.y + ry * nh.y);
            float hx = featT[c * 8 + 2 * p];
            float hy = featT[c * 8 + 2 * p + 1];
            hn[2 * p]     = nx + zx * (hx - nx);   // (1-z)*n + z*h
            hn[2 * p + 1] = ny + zy * (hy - ny);
        }
        __syncthreads();   // everyone done reading old h
        *reinterpret_cast<float4*>(featT + c * 8) =
            make_float4(hn[0], hn[1], hn[2], hn[3]);
        *reinterpret_cast<float4*>(featT + c * 8 + 4) =
            make_float4(hn[4], hn[5], hn[6], hn[7]);

        do_heads(featT, red, out, b0, step + 1, bmu, blv);  // starts with sync
    }
}

// ---------------------------------------------------------------------------
extern "C" void kernel_launch(void* const* d_in, const int* in_sizes, int n_in,
                              void* d_out, int out_size) {
    const float* xl  = (const float*)d_in[0];   // x_l_seq   [1024,168,64]
    const float* xe  = (const float*)d_in[1];   // x_ext_seq [1024,168,16]
    const float* z   = (const float*)d_in[2];   // z_latent  [1024,512]
    const float* Wih = (const float*)d_in[3];   // [1536,256]
    const float* Whh = (const float*)d_in[4];   // [1536,512]
    const float* bih = (const float*)d_in[5];   // [1536]
    const float* bhh = (const float*)d_in[6];   // [1536]
    const float* Wmu = (const float*)d_in[7];   // [24,512]
    const float* bmu = (const float*)d_in[8];   // [24]
    const float* Wlv = (const float*)d_in[9];   // [24,512]
    const float* blv = (const float*)d_in[10];  // [24]
    const float* Wtb = (const float*)d_in[11];  // [592,256]
    const float* btb = (const float*)d_in[12];  // [256]
    float* out = (float*)d_out;                 // mu [1024,169,24] then lv

    prep_kernel<<<256, 256>>>(Wih, Whh, Wmu, Wlv, Wtb);
    decoder_kernel<<<NCTA, NT>>>(xl, xe, z, bih, bhh, bmu, blv, btb, out);
}